// round 6
// baseline (speedup 1.0000x reference)
#include <cuda_runtime.h>
#include <cuda_fp16.h>
#include <math.h>
#include <stdint.h>

#define B_ 32
#define T_ 1024
#define D_ 512
#define H_ 2048
#define E_ 8

#define BM 128
#define BN 128
#define BK 32                    // halves per k-tile (2 x k16 mma steps)
#define STAGES 5

#define RSTR 40                               // halves per smem row (32 data + 8 pad)
#define RSTRB (RSTR * 2)                      // 80 bytes
#define A_BYTES (BM * RSTRB)                  // 10240
#define B_BYTES (BN * RSTRB)                  // 10240
#define STAGE_BYTES (A_BYTES + B_BYTES)       // 20480
#define SMEMSZ (STAGES * STAGE_BYTES)         // 102400

// ---------------------------------------------------------------------------
// scratch (device globals — no allocation allowed)
// ---------------------------------------------------------------------------
__device__ int    g_eidx[B_][2];
__device__ float  g_prob[B_][2];
__device__ float  g_pool[B_][8][D_];
__device__ __half g_xh[(size_t)B_ * T_ * D_];        // fp16 x
__device__ __half g_w1t[(size_t)E_ * H_ * D_];       // w1^T [E][H][D] fp16
__device__ __half g_w2t[(size_t)E_ * D_ * H_];       // w2^T [E][D][H] fp16
__device__ __half g_h[(size_t)B_ * T_ * (2 * H_)];   // p*silu(x@w1+b1) fp16

// ---------------------------------------------------------------------------
// helpers
// ---------------------------------------------------------------------------
__device__ __forceinline__ uint32_t smem_u32(const void* p) {
    uint32_t a;
    asm("{ .reg .u64 t; cvta.to.shared.u64 t, %1; cvt.u32.u64 %0, t; }" : "=r"(a) : "l"(p));
    return a;
}
__device__ __forceinline__ void cp16(uint32_t dst, const void* src) {
    asm volatile("cp.async.cg.shared.global [%0], [%1], 16;" :: "r"(dst), "l"(src));
}
__device__ __forceinline__ void cp_commit() {
    asm volatile("cp.async.commit_group;" ::: "memory");
}
template <int N>
__device__ __forceinline__ void cp_wait() {
    asm volatile("cp.async.wait_group %0;" :: "n"(N) : "memory");
}
__device__ __forceinline__ void ldsm_x4(unsigned& r0, unsigned& r1, unsigned& r2,
                                        unsigned& r3, uint32_t addr) {
    asm volatile("ldmatrix.sync.aligned.m8n8.x4.shared.b16 {%0,%1,%2,%3}, [%4];"
        : "=r"(r0), "=r"(r1), "=r"(r2), "=r"(r3) : "r"(addr));
}
__device__ __forceinline__ void ldsm_x2(unsigned& r0, unsigned& r1, uint32_t addr) {
    asm volatile("ldmatrix.sync.aligned.m8n8.x2.shared.b16 {%0,%1}, [%2];"
        : "=r"(r0), "=r"(r1) : "r"(addr));
}
__device__ __forceinline__ void mma_f16(float* d, const unsigned* a, const unsigned* b) {
    asm volatile(
        "mma.sync.aligned.m16n8k16.row.col.f32.f16.f16.f32 "
        "{%0,%1,%2,%3}, {%4,%5,%6,%7}, {%8,%9}, {%0,%1,%2,%3};\n"
        : "+f"(d[0]), "+f"(d[1]), "+f"(d[2]), "+f"(d[3])
        : "r"(a[0]), "r"(a[1]), "r"(a[2]), "r"(a[3]), "r"(b[0]), "r"(b[1]));
}

// ---------------------------------------------------------------------------
// prep kernels
// ---------------------------------------------------------------------------
__global__ void pool_convert_kernel(const float* __restrict__ x) {
    const int b = blockIdx.x, ch = blockIdx.y, d = threadIdx.x;   // 512 threads
    const size_t base = ((size_t)b * T_ + (size_t)ch * 128) * D_ + d;
    float s = 0.f;
    for (int t = 0; t < 128; t++) {
        float v = x[base + (size_t)t * D_];
        s += v;
        g_xh[base + (size_t)t * D_] = __float2half_rn(v);
    }
    g_pool[b][ch][d] = s;
}

// tiled transpose + fp16: src [E][R][C] float -> dst [E][C][R] half
__global__ void transpose_rc_kernel(const float* __restrict__ src, __half* __restrict__ dst,
                                    int R, int C) {
    __shared__ float tile[32][33];
    const int e = blockIdx.z;
    const float* S = src + (size_t)e * R * C;
    __half* Dp = dst + (size_t)e * R * C;
    const int c0 = blockIdx.x * 32, r0 = blockIdx.y * 32;
    const int tx = threadIdx.x, ty = threadIdx.y;
    #pragma unroll
    for (int i = 0; i < 4; i++)
        tile[ty + i * 8][tx] = S[(size_t)(r0 + ty + i * 8) * C + c0 + tx];
    __syncthreads();
    #pragma unroll
    for (int i = 0; i < 4; i++)
        Dp[(size_t)(c0 + ty + i * 8) * R + r0 + tx] = __float2half_rn(tile[tx][ty + i * 8]);
}

__global__ void gate_kernel(const float* __restrict__ gw, const float* __restrict__ gb,
                            float* __restrict__ out_logits) {
    __shared__ float pooled[D_];
    __shared__ float logits[E_];
    const int b = blockIdx.x, d = threadIdx.x;
    float s = 0.f;
    #pragma unroll
    for (int c = 0; c < 8; c++) s += g_pool[b][c][d];
    pooled[d] = s * (1.0f / (float)T_);
    __syncthreads();
    const int w = threadIdx.x >> 5, lane = threadIdx.x & 31;
    if (w < E_) {
        float acc = 0.f;
        for (int j = lane; j < D_; j += 32) acc += pooled[j] * gw[(size_t)j * E_ + w];
        #pragma unroll
        for (int o = 16; o > 0; o >>= 1) acc += __shfl_xor_sync(0xffffffffu, acc, o);
        if (lane == 0) logits[w] = acc + gb[w];
    }
    __syncthreads();
    if (threadIdx.x == 0) {
        int i0 = 0; float l0 = logits[0];
        for (int e = 1; e < E_; e++) if (logits[e] > l0) { l0 = logits[e]; i0 = e; }
        int i1 = -1; float l1 = -1e30f;
        for (int e = 0; e < E_; e++) if (e != i0 && logits[e] > l1) { l1 = logits[e]; i1 = e; }
        float e1 = expf(l1 - l0);
        float inv = 1.0f / (1.0f + e1);
        g_eidx[b][0] = i0; g_eidx[b][1] = i1;
        g_prob[b][0] = inv; g_prob[b][1] = e1 * inv;
        for (int e = 0; e < E_; e++) out_logits[b * E_ + e] = logits[e];
    }
}

// ---------------------------------------------------------------------------
// GEMM core: 128 threads, 4 warps 2(m)x2(n), warp tile 64x64, fp16 m16n8k16
// A smem [BM][RSTR] halves (k contiguous); B smem [BN][RSTR] (k contiguous)
// Fragment loads via ldmatrix.
// ---------------------------------------------------------------------------

// each thread issues 4 A-chunks + 4 B-chunks (16B each) per stage
#define ISSUE_STAGE(slot, A_SRC, B_SRC) do {                                   \
    const uint32_t _as = sm_base + (slot) * STAGE_BYTES;                       \
    const uint32_t _bs = _as + A_BYTES;                                        \
    _Pragma("unroll")                                                          \
    for (int _i = 0; _i < 4; _i++) {                                           \
        const int _c = _i * 128 + tid;                                         \
        const int _r = _c >> 2, _cc = _c & 3;                                  \
        cp16(_as + _r * RSTRB + _cc * 16, (A_SRC(_r, _cc)));                   \
    }                                                                          \
    _Pragma("unroll")                                                          \
    for (int _i = 0; _i < 4; _i++) {                                           \
        const int _c = _i * 128 + tid;                                         \
        const int _r = _c >> 2, _cc = _c & 3;                                  \
        cp16(_bs + _r * RSTRB + _cc * 16, (B_SRC(_r, _cc)));                   \
    }                                                                          \
} while (0)

#define COMPUTE_STAGE(slot) do {                                               \
    const uint32_t _a0 = sm_base + (slot) * STAGE_BYTES + offA;                \
    const uint32_t _b0 = sm_base + (slot) * STAGE_BYTES + A_BYTES + offB;      \
    _Pragma("unroll")                                                          \
    for (int ks = 0; ks < 2; ks++) {                                           \
        unsigned af[4][4], bf[8][2];                                           \
        _Pragma("unroll")                                                      \
        for (int mt = 0; mt < 4; mt++)                                         \
            ldsm_x4(af[mt][0], af[mt][1], af[mt][2], af[mt][3],                \
                    _a0 + mt * (16 * RSTRB) + ks * 32);                        \
        _Pragma("unroll")                                                      \
        for (int nt = 0; nt < 8; nt++)                                         \
            ldsm_x2(bf[nt][0], bf[nt][1], _b0 + nt * (8 * RSTRB) + ks * 32);   \
        _Pragma("unroll")                                                      \
        for (int mt = 0; mt < 4; mt++)                                         \
            _Pragma("unroll")                                                  \
            for (int nt = 0; nt < 8; nt++)                                     \
                mma_f16(acc[mt][nt], af[mt], bf[nt]);                          \
    }                                                                          \
} while (0)

#define GEMM_PIPELINE(NK, A_SRC, B_SRC) do {                                   \
    _Pragma("unroll")                                                          \
    for (int s = 0; s < STAGES - 1; s++) {                                     \
        const int kk = s;                                                      \
        ISSUE_STAGE(s, A_SRC, B_SRC);                                          \
        cp_commit();                                                           \
    }                                                                          \
    for (int kt = 0; kt < (NK); kt++) {                                        \
        cp_wait<STAGES - 2>();                                                 \
        __syncthreads();                                                       \
        const int pf = kt + STAGES - 1;                                        \
        if (pf < (NK)) {                                                       \
            const int kk = pf;                                                 \
            ISSUE_STAGE(pf % STAGES, A_SRC, B_SRC);                            \
        }                                                                      \
        cp_commit();                                                           \
        COMPUTE_STAGE(kt % STAGES);                                            \
    }                                                                          \
} while (0)

// ldmatrix lane offsets (bytes within A / B tile)
#define LANE_OFFS()                                                            \
    const int wm = (warp & 1) * 64;                                            \
    const int wn = (warp >> 1) * 64;                                           \
    const uint32_t offA = (uint32_t)(wm + (lane & 15)) * RSTRB + (uint32_t)(lane >> 4) * 16; \
    const uint32_t offB = (uint32_t)(wn + (lane & 7)) * RSTRB + (uint32_t)((lane >> 3) & 1) * 16;

// ---------------------------------------------------------------------------
// GEMM1: h[b][t][slot*H + n] = fp16( p * silu( xh[b] @ w1t[e]^T + b1[e] ) )
// grid (H/BN=16, T/BM=8, B*2=64), 128 threads
// ---------------------------------------------------------------------------
__global__ __launch_bounds__(128, 2) void gemm1_kernel(const float* __restrict__ b1) {
    extern __shared__ char smem[];
    const uint32_t sm_base = smem_u32(smem);

    const int bz = blockIdx.z, b = bz >> 1, slot = bz & 1;
    const int e = g_eidx[b][slot];
    const float p = g_prob[b][slot];
    const int m0 = blockIdx.y * BM;
    const int n0 = blockIdx.x * BN;
    const int tid  = threadIdx.x;
    const int warp = tid >> 5, lane = tid & 31;
    LANE_OFFS();

    const __half* Ag = g_xh  + ((size_t)b * T_ + m0) * D_;
    const __half* Bg = g_w1t + ((size_t)e * H_ + n0) * D_;

    float acc[4][8][4];
    #pragma unroll
    for (int i = 0; i < 4; i++)
        #pragma unroll
        for (int j = 0; j < 8; j++)
            #pragma unroll
            for (int r = 0; r < 4; r++) acc[i][j][r] = 0.f;

    #define A1(r, c) (Ag + (size_t)(r) * D_ + kk * BK + (c) * 8)
    #define B1(r, c) (Bg + (size_t)(r) * D_ + kk * BK + (c) * 8)
    GEMM_PIPELINE(D_ / BK, A1, B1);      // 16 k-tiles
    #undef A1
    #undef B1

    // epilogue: +b1, silu, *p, fp16, write h
    const int g = lane >> 2, t4 = lane & 3;
    const float* brow = b1 + (size_t)e * H_ + n0;
    __half* Hb = g_h + ((size_t)b * T_ + m0) * (2 * H_) + (size_t)slot * H_ + n0;
    #pragma unroll
    for (int mt = 0; mt < 4; mt++) {
        #pragma unroll
        for (int nt = 0; nt < 8; nt++) {
            #pragma unroll
            for (int half = 0; half < 2; half++) {
                const int row = wm + mt * 16 + g + half * 8;
                const int col = wn + nt * 8 + t4 * 2;
                float v0 = acc[mt][nt][half * 2 + 0] + brow[col];
                float v1 = acc[mt][nt][half * 2 + 1] + brow[col + 1];
                v0 = p * v0 * (1.0f / (1.0f + __expf(-v0)));
                v1 = p * v1 * (1.0f / (1.0f + __expf(-v1)));
                *(__half2*)&Hb[(size_t)row * (2 * H_) + col] =
                    __floats2half2_rn(v0, v1);
            }
        }
    }
}

// ---------------------------------------------------------------------------
// GEMM2: out[b] = h_cat[b] @ [w2t[e0]; w2t[e1]]^T + p0*b2[e0] + p1*b2[e1] + x[b]
// grid (D/BN=4, T/BM=8, B=32), 128 threads
// ---------------------------------------------------------------------------
__global__ __launch_bounds__(128, 2) void gemm2_kernel(const float* __restrict__ x,
                                                       const float* __restrict__ b2,
                                                       float* __restrict__ out) {
    extern __shared__ char smem[];
    const uint32_t sm_base = smem_u32(smem);

    const int b = blockIdx.z;
    const int e0 = g_eidx[b][0], e1 = g_eidx[b][1];
    const float p0 = g_prob[b][0], p1 = g_prob[b][1];
    const int m0 = blockIdx.y * BM;
    const int n0 = blockIdx.x * BN;
    const int tid  = threadIdx.x;
    const int warp = tid >> 5, lane = tid & 31;
    LANE_OFFS();

    const __half* Ag  = g_h + ((size_t)b * T_ + m0) * (2 * H_);
    const __half* Bg0 = g_w2t + ((size_t)e0 * D_ + n0) * H_;
    const __half* Bg1 = g_w2t + ((size_t)e1 * D_ + n0) * H_;

    float acc[4][8][4];
    #pragma unroll
    for (int i = 0; i < 4; i++)
        #pragma unroll
        for (int j = 0; j < 8; j++)
            #pragma unroll
            for (int r = 0; r < 4; r++) acc[i][j][r] = 0.f;

    #define A2(r, c) (Ag + (size_t)(r) * (2 * H_) + kk * BK + (c) * 8)
    #define B2(r, c) ((kk < 64 ? Bg0 : Bg1) + (size_t)(r) * H_ + (kk & 63) * BK + (c) * 8)
    GEMM_PIPELINE((2 * H_) / BK, A2, B2);    // 128 k-tiles
    #undef A2
    #undef B2

    // epilogue: + p0*b2[e0] + p1*b2[e1] + x, write out (fp32)
    const int g = lane >> 2, t4 = lane & 3;
    const float* b2r0 = b2 + (size_t)e0 * D_ + n0;
    const float* b2r1 = b2 + (size_t)e1 * D_ + n0;
    const float* xb = x   + ((size_t)b * T_ + m0) * D_ + n0;
    float*       ob = out + ((size_t)b * T_ + m0) * D_ + n0;
    #pragma unroll
    for (int mt = 0; mt < 4; mt++) {
        #pragma unroll
        for (int nt = 0; nt < 8; nt++) {
            #pragma unroll
            for (int half = 0; half < 2; half++) {
                const int row = wm + mt * 16 + g + half * 8;
                const int col = wn + nt * 8 + t4 * 2;
                const float bias0 = p0 * b2r0[col]     + p1 * b2r1[col];
                const float bias1 = p0 * b2r0[col + 1] + p1 * b2r1[col + 1];
                const float2 xv = *(const float2*)&xb[(size_t)row * D_ + col];
                float v0 = acc[mt][nt][half * 2 + 0] + bias0 + xv.x;
                float v1 = acc[mt][nt][half * 2 + 1] + bias1 + xv.y;
                *(float2*)&ob[(size_t)row * D_ + col] = make_float2(v0, v1);
            }
        }
    }
}

// ---------------------------------------------------------------------------
extern "C" void kernel_launch(void* const* d_in, const int* in_sizes, int n_in,
                              void* d_out, int out_size) {
    const float* x  = (const float*)d_in[0];
    const float* gw = (const float*)d_in[1];
    const float* gb = (const float*)d_in[2];
    const float* w1 = (const float*)d_in[3];
    const float* b1 = (const float*)d_in[4];
    const float* w2 = (const float*)d_in[5];
    const float* b2 = (const float*)d_in[6];

    float* out = (float*)d_out;
    float* out_logits = out + (size_t)B_ * T_ * D_;

    cudaFuncSetAttribute(gemm1_kernel, cudaFuncAttributeMaxDynamicSharedMemorySize, SMEMSZ);
    cudaFuncSetAttribute(gemm2_kernel, cudaFuncAttributeMaxDynamicSharedMemorySize, SMEMSZ);

    pool_convert_kernel<<<dim3(B_, 8), 512>>>(x);
    {
        __half* w1t_ptr; cudaGetSymbolAddress((void**)&w1t_ptr, g_w1t);
        __half* w2t_ptr; cudaGetSymbolAddress((void**)&w2t_ptr, g_w2t);
        transpose_rc_kernel<<<dim3(H_ / 32, D_ / 32, E_), dim3(32, 8)>>>(w1, w1t_ptr, D_, H_);
        transpose_rc_kernel<<<dim3(D_ / 32, H_ / 32, E_), dim3(32, 8)>>>(w2, w2t_ptr, H_, D_);
    }
    gate_kernel<<<B_, 512>>>(gw, gb, out_logits);

    gemm1_kernel<<<dim3(H_ / BN, T_ / BM, B_ * 2), 128, SMEMSZ>>>(b1);
    gemm2_kernel<<<dim3(D_ / BN, T_ / BM, B_), 128, SMEMSZ>>>(x, b2, out);
}

// round 7
// speedup vs baseline: 1.3531x; 1.3531x over previous
#include <cuda_runtime.h>
#include <cuda_fp16.h>
#include <math.h>
#include <stdint.h>

#define B_ 32
#define T_ 1024
#define D_ 512
#define H_ 2048
#define E_ 8

#define BM 128
#define BN 128
#define BK 64                    // halves per k-tile (4 x k16 mma steps), 128B rows
#define STAGES 3

#define A_BYTES (BM * 128)                    // 16384
#define B_BYTES (BN * 128)                    // 16384
#define STAGE_BYTES (A_BYTES + B_BYTES)       // 32768
#define SMEMSZ (STAGES * STAGE_BYTES)         // 98304

// ---------------------------------------------------------------------------
// scratch (device globals — no allocation allowed)
// ---------------------------------------------------------------------------
__device__ int      g_eidx[B_][2];
__device__ float    g_prob[B_][2];
__device__ float    g_pool[B_][8][D_];
__device__ unsigned g_cnt[B_][8];                    // gemm1->gemm2 readiness
__device__ __half   g_xh[(size_t)B_ * T_ * D_];      // fp16 x
__device__ __half   g_w1t[(size_t)E_ * H_ * D_];     // w1^T [E][H][D] fp16
__device__ __half   g_w2t[(size_t)E_ * D_ * H_];     // w2^T [E][D][H] fp16
__device__ __half   g_h[(size_t)B_ * T_ * (2 * H_)]; // p*silu(x@w1+b1) fp16

// ---------------------------------------------------------------------------
// helpers
// ---------------------------------------------------------------------------
__device__ __forceinline__ uint32_t smem_u32(const void* p) {
    uint32_t a;
    asm("{ .reg .u64 t; cvta.to.shared.u64 t, %1; cvt.u32.u64 %0, t; }" : "=r"(a) : "l"(p));
    return a;
}
__device__ __forceinline__ void cp16(uint32_t dst, const void* src) {
    asm volatile("cp.async.cg.shared.global [%0], [%1], 16;" :: "r"(dst), "l"(src));
}
__device__ __forceinline__ void cp_commit() {
    asm volatile("cp.async.commit_group;" ::: "memory");
}
template <int N>
__device__ __forceinline__ void cp_wait() {
    asm volatile("cp.async.wait_group %0;" :: "n"(N) : "memory");
}
__device__ __forceinline__ void ldsm_x4(unsigned& r0, unsigned& r1, unsigned& r2,
                                        unsigned& r3, uint32_t addr) {
    asm volatile("ldmatrix.sync.aligned.m8n8.x4.shared.b16 {%0,%1,%2,%3}, [%4];"
        : "=r"(r0), "=r"(r1), "=r"(r2), "=r"(r3) : "r"(addr));
}
__device__ __forceinline__ void ldsm_x2(unsigned& r0, unsigned& r1, uint32_t addr) {
    asm volatile("ldmatrix.sync.aligned.m8n8.x2.shared.b16 {%0,%1}, [%2];"
        : "=r"(r0), "=r"(r1) : "r"(addr));
}
__device__ __forceinline__ void mma_f16(float* d, const unsigned* a, const unsigned* b) {
    asm volatile(
        "mma.sync.aligned.m16n8k16.row.col.f32.f16.f16.f32 "
        "{%0,%1,%2,%3}, {%4,%5,%6,%7}, {%8,%9}, {%0,%1,%2,%3};\n"
        : "+f"(d[0]), "+f"(d[1]), "+f"(d[2]), "+f"(d[3])
        : "r"(a[0]), "r"(a[1]), "r"(a[2]), "r"(a[3]), "r"(b[0]), "r"(b[1]));
}

// ---------------------------------------------------------------------------
// prep kernels
// ---------------------------------------------------------------------------
__global__ void pool_convert_kernel(const float* __restrict__ x) {
    const int b = blockIdx.x, ch = blockIdx.y, d = threadIdx.x;   // 512 threads
    if (threadIdx.x == 0) g_cnt[b][ch] = 0u;                      // reset fusion counters
    const size_t base = ((size_t)b * T_ + (size_t)ch * 128) * D_ + d;
    float s = 0.f;
    for (int t = 0; t < 128; t++) {
        float v = x[base + (size_t)t * D_];
        s += v;
        g_xh[base + (size_t)t * D_] = __float2half_rn(v);
    }
    g_pool[b][ch][d] = s;
}

// tiled transpose + fp16: src [E][R][C] float -> dst [E][C][R] half
__global__ void transpose_rc_kernel(const float* __restrict__ src, __half* __restrict__ dst,
                                    int R, int C) {
    __shared__ float tile[32][33];
    const int e = blockIdx.z;
    const float* S = src + (size_t)e * R * C;
    __half* Dp = dst + (size_t)e * R * C;
    const int c0 = blockIdx.x * 32, r0 = blockIdx.y * 32;
    const int tx = threadIdx.x, ty = threadIdx.y;
    #pragma unroll
    for (int i = 0; i < 4; i++)
        tile[ty + i * 8][tx] = S[(size_t)(r0 + ty + i * 8) * C + c0 + tx];
    __syncthreads();
    #pragma unroll
    for (int i = 0; i < 4; i++)
        Dp[(size_t)(c0 + ty + i * 8) * R + r0 + tx] = __float2half_rn(tile[tx][ty + i * 8]);
}

__global__ void gate_kernel(const float* __restrict__ gw, const float* __restrict__ gb,
                            float* __restrict__ out_logits) {
    __shared__ float pooled[D_];
    __shared__ float logits[E_];
    const int b = blockIdx.x, d = threadIdx.x;
    float s = 0.f;
    #pragma unroll
    for (int c = 0; c < 8; c++) s += g_pool[b][c][d];
    pooled[d] = s * (1.0f / (float)T_);
    __syncthreads();
    const int w = threadIdx.x >> 5, lane = threadIdx.x & 31;
    if (w < E_) {
        float acc = 0.f;
        for (int j = lane; j < D_; j += 32) acc += pooled[j] * gw[(size_t)j * E_ + w];
        #pragma unroll
        for (int o = 16; o > 0; o >>= 1) acc += __shfl_xor_sync(0xffffffffu, acc, o);
        if (lane == 0) logits[w] = acc + gb[w];
    }
    __syncthreads();
    if (threadIdx.x == 0) {
        int i0 = 0; float l0 = logits[0];
        for (int e = 1; e < E_; e++) if (logits[e] > l0) { l0 = logits[e]; i0 = e; }
        int i1 = -1; float l1 = -1e30f;
        for (int e = 0; e < E_; e++) if (e != i0 && logits[e] > l1) { l1 = logits[e]; i1 = e; }
        float e1 = expf(l1 - l0);
        float inv = 1.0f / (1.0f + e1);
        g_eidx[b][0] = i0; g_eidx[b][1] = i1;
        g_prob[b][0] = inv; g_prob[b][1] = e1 * inv;
        for (int e = 0; e < E_; e++) out_logits[b * E_ + e] = logits[e];
    }
}

// ---------------------------------------------------------------------------
// GEMM core: 256 threads, 8 warps 2(m)x4(n), warp tile 64x32, fp16 m16n8k16
// Tiles: 128 rows x 128B (64 halves), XOR-swizzled: chunk_phys = chunk ^ (row&7)
// ---------------------------------------------------------------------------

// per stage: A 1024 chunks + B 1024 chunks; 256 threads -> 4+4 cp16 each
#define ISSUE_STAGE(slot, A_SRC, B_SRC) do {                                   \
    const uint32_t _as = sm_base + (slot) * STAGE_BYTES;                       \
    const uint32_t _bs = _as + A_BYTES;                                        \
    _Pragma("unroll")                                                          \
    for (int _i = 0; _i < 4; _i++) {                                           \
        const int _c = _i * 256 + tid;                                         \
        const int _r = _c >> 3, _lc = _c & 7;                                  \
        cp16(_as + _r * 128 + ((_lc ^ (_r & 7)) << 4), (A_SRC(_r, _lc)));      \
    }                                                                          \
    _Pragma("unroll")                                                          \
    for (int _i = 0; _i < 4; _i++) {                                           \
        const int _c = _i * 256 + tid;                                         \
        const int _r = _c >> 3, _lc = _c & 7;                                  \
        cp16(_bs + _r * 128 + ((_lc ^ (_r & 7)) << 4), (B_SRC(_r, _lc)));      \
    }                                                                          \
} while (0)

#define COMPUTE_STAGE(slot) do {                                               \
    const uint32_t _ab = sm_base + (slot) * STAGE_BYTES;                       \
    const uint32_t _bb = _ab + A_BYTES;                                        \
    _Pragma("unroll")                                                          \
    for (int ks = 0; ks < 4; ks++) {                                           \
        unsigned af[4][4], bf[4][2];                                           \
        _Pragma("unroll")                                                      \
        for (int mt = 0; mt < 4; mt++)                                         \
            ldsm_x4(af[mt][0], af[mt][1], af[mt][2], af[mt][3],                \
                    _ab + arow_off + mt * 2048 + (((2 * ks + ac) ^ sxor) << 4)); \
        _Pragma("unroll")                                                      \
        for (int nt = 0; nt < 4; nt++)                                         \
            ldsm_x2(bf[nt][0], bf[nt][1],                                      \
                    _bb + brow_off + nt * 1024 + (((2 * ks + bc) ^ sxor) << 4)); \
        _Pragma("unroll")                                                      \
        for (int mt = 0; mt < 4; mt++)                                         \
            _Pragma("unroll")                                                  \
            for (int nt = 0; nt < 4; nt++)                                     \
                mma_f16(acc[mt][nt], af[mt], bf[nt]);                          \
    }                                                                          \
} while (0)

#define GEMM_PIPELINE(NK, A_SRC, B_SRC) do {                                   \
    _Pragma("unroll")                                                          \
    for (int s = 0; s < STAGES - 1; s++) {                                     \
        const int kk = s;                                                      \
        ISSUE_STAGE(s, A_SRC, B_SRC);                                          \
        cp_commit();                                                           \
    }                                                                          \
    for (int kt = 0; kt < (NK); kt++) {                                        \
        cp_wait<STAGES - 2>();                                                 \
        __syncthreads();                                                       \
        const int pf = kt + STAGES - 1;                                        \
        if (pf < (NK)) {                                                       \
            const int kk = pf;                                                 \
            ISSUE_STAGE(pf % STAGES, A_SRC, B_SRC);                            \
        }                                                                      \
        cp_commit();                                                           \
        COMPUTE_STAGE(kt % STAGES);                                            \
    }                                                                          \
} while (0)

#define LANE_OFFS()                                                            \
    const int wm = (warp & 1) * 64;                                            \
    const int wn = (warp >> 1) * 32;                                           \
    const uint32_t arow_off = (uint32_t)(wm + (lane & 15)) * 128;              \
    const uint32_t ac = (uint32_t)(lane >> 4);                                 \
    const uint32_t brow_off = (uint32_t)(wn + (lane & 7)) * 128;               \
    const uint32_t bc = (uint32_t)((lane >> 3) & 1);                           \
    const uint32_t sxor = (uint32_t)(lane & 7);

// ---------------------------------------------------------------------------
// GEMM1: h[b][t][slot*H + n] = fp16( p * silu( xh[b] @ w1t[e]^T + b1[e] ) )
// grid (H/BN=16, T/BM=8, B*2=64), 256 threads
// ---------------------------------------------------------------------------
__global__ __launch_bounds__(256, 2) void gemm1_kernel(const float* __restrict__ b1) {
    extern __shared__ char smem[];
    const uint32_t sm_base = smem_u32(smem);

    const int bz = blockIdx.z, b = bz >> 1, slot = bz & 1;
    const int e = g_eidx[b][slot];
    const float p = g_prob[b][slot];
    const int m0 = blockIdx.y * BM;
    const int n0 = blockIdx.x * BN;
    const int tid  = threadIdx.x;
    const int warp = tid >> 5, lane = tid & 31;
    LANE_OFFS();

    const __half* Ag = g_xh  + ((size_t)b * T_ + m0) * D_;
    const __half* Bg = g_w1t + ((size_t)e * H_ + n0) * D_;

    float acc[4][4][4];
    #pragma unroll
    for (int i = 0; i < 4; i++)
        #pragma unroll
        for (int j = 0; j < 4; j++)
            #pragma unroll
            for (int r = 0; r < 4; r++) acc[i][j][r] = 0.f;

    #define A1(r, c) (Ag + (size_t)(r) * D_ + kk * BK + (c) * 8)
    #define B1(r, c) (Bg + (size_t)(r) * D_ + kk * BK + (c) * 8)
    GEMM_PIPELINE(D_ / BK, A1, B1);      // 8 k-tiles
    #undef A1
    #undef B1

    // epilogue: +b1, silu, *p, fp16, write h
    const int g = lane >> 2, t4 = lane & 3;
    const float* brow = b1 + (size_t)e * H_ + n0;
    __half* Hb = g_h + ((size_t)b * T_ + m0) * (2 * H_) + (size_t)slot * H_ + n0;
    #pragma unroll
    for (int mt = 0; mt < 4; mt++) {
        #pragma unroll
        for (int nt = 0; nt < 4; nt++) {
            #pragma unroll
            for (int half = 0; half < 2; half++) {
                const int row = wm + mt * 16 + g + half * 8;
                const int col = wn + nt * 8 + t4 * 2;
                float v0 = acc[mt][nt][half * 2 + 0] + brow[col];
                float v1 = acc[mt][nt][half * 2 + 1] + brow[col + 1];
                v0 = p * v0 * (1.0f / (1.0f + __expf(-v0)));
                v1 = p * v1 * (1.0f / (1.0f + __expf(-v1)));
                *(__half2*)&Hb[(size_t)row * (2 * H_) + col] =
                    __floats2half2_rn(v0, v1);
            }
        }
    }

    // release: signal (b, m-tile) readiness for gemm2
    __syncthreads();
    if (tid == 0) {
        __threadfence();
        atomicAdd(&g_cnt[b][blockIdx.y], 1u);
    }
}

// ---------------------------------------------------------------------------
// GEMM2: out[b] = h_cat[b] @ [w2t[e0]; w2t[e1]]^T + p0*b2[e0] + p1*b2[e1] + x[b]
// grid (D/BN=4, T/BM=8, B=32), 256 threads
// ---------------------------------------------------------------------------
__global__ __launch_bounds__(256, 2) void gemm2_kernel(const float* __restrict__ x,
                                                       const float* __restrict__ b2,
                                                       float* __restrict__ out) {
    extern __shared__ char smem[];
    const uint32_t sm_base = smem_u32(smem);

    const int b = blockIdx.z;
    const int m0 = blockIdx.y * BM;
    const int n0 = blockIdx.x * BN;
    const int tid  = threadIdx.x;
    const int warp = tid >> 5, lane = tid & 31;
    LANE_OFFS();

    // acquire: wait until the 32 gemm1 CTAs covering (b, m-tile) have finished
    if (tid == 0) {
        while (atomicAdd(&g_cnt[b][blockIdx.y], 0u) < 32u) { __nanosleep(64); }
        __threadfence();
    }
    __syncthreads();

    const int e0 = g_eidx[b][0], e1 = g_eidx[b][1];
    const float p0 = g_prob[b][0], p1 = g_prob[b][1];
    const __half* Ag  = g_h + ((size_t)b * T_ + m0) * (2 * H_);
    const __half* Bg0 = g_w2t + ((size_t)e0 * D_ + n0) * H_;
    const __half* Bg1 = g_w2t + ((size_t)e1 * D_ + n0) * H_;

    float acc[4][4][4];
    #pragma unroll
    for (int i = 0; i < 4; i++)
        #pragma unroll
        for (int j = 0; j < 4; j++)
            #pragma unroll
            for (int r = 0; r < 4; r++) acc[i][j][r] = 0.f;

    #define A2(r, c) (Ag + (size_t)(r) * (2 * H_) + kk * BK + (c) * 8)
    #define B2(r, c) ((kk < 32 ? Bg0 : Bg1) + (size_t)(r) * H_ + (kk & 31) * BK + (c) * 8)
    GEMM_PIPELINE((2 * H_) / BK, A2, B2);    // 64 k-tiles
    #undef A2
    #undef B2

    // epilogue: + p0*b2[e0] + p1*b2[e1] + x, write out (fp32)
    const int g = lane >> 2, t4 = lane & 3;
    const float* b2r0 = b2 + (size_t)e0 * D_ + n0;
    const float* b2r1 = b2 + (size_t)e1 * D_ + n0;
    const float* xb = x   + ((size_t)b * T_ + m0) * D_ + n0;
    float*       ob = out + ((size_t)b * T_ + m0) * D_ + n0;
    #pragma unroll
    for (int mt = 0; mt < 4; mt++) {
        #pragma unroll
        for (int nt = 0; nt < 4; nt++) {
            #pragma unroll
            for (int half = 0; half < 2; half++) {
                const int row = wm + mt * 16 + g + half * 8;
                const int col = wn + nt * 8 + t4 * 2;
                const float bias0 = p0 * b2r0[col]     + p1 * b2r1[col];
                const float bias1 = p0 * b2r0[col + 1] + p1 * b2r1[col + 1];
                const float2 xv = *(const float2*)&xb[(size_t)row * D_ + col];
                float v0 = acc[mt][nt][half * 2 + 0] + bias0 + xv.x;
                float v1 = acc[mt][nt][half * 2 + 1] + bias1 + xv.y;
                *(float2*)&ob[(size_t)row * D_ + col] = make_float2(v0, v1);
            }
        }
    }
}

// ---------------------------------------------------------------------------
extern "C" void kernel_launch(void* const* d_in, const int* in_sizes, int n_in,
                              void* d_out, int out_size) {
    const float* x  = (const float*)d_in[0];
    const float* gw = (const float*)d_in[1];
    const float* gb = (const float*)d_in[2];
    const float* w1 = (const float*)d_in[3];
    const float* b1 = (const float*)d_in[4];
    const float* w2 = (const float*)d_in[5];
    const float* b2 = (const float*)d_in[6];

    float* out = (float*)d_out;
    float* out_logits = out + (size_t)B_ * T_ * D_;

    cudaFuncSetAttribute(gemm1_kernel, cudaFuncAttributeMaxDynamicSharedMemorySize, SMEMSZ);
    cudaFuncSetAttribute(gemm2_kernel, cudaFuncAttributeMaxDynamicSharedMemorySize, SMEMSZ);

    pool_convert_kernel<<<dim3(B_, 8), 512>>>(x);
    {
        __half* w1t_ptr; cudaGetSymbolAddress((void**)&w1t_ptr, g_w1t);
        __half* w2t_ptr; cudaGetSymbolAddress((void**)&w2t_ptr, g_w2t);
        transpose_rc_kernel<<<dim3(H_ / 32, D_ / 32, E_), dim3(32, 8)>>>(w1, w1t_ptr, D_, H_);
        transpose_rc_kernel<<<dim3(D_ / 32, H_ / 32, E_), dim3(32, 8)>>>(w2, w2t_ptr, H_, D_);
    }
    gate_kernel<<<B_, 512>>>(gw, gb, out_logits);

    gemm1_kernel<<<dim3(H_ / BN, T_ / BM, B_ * 2), 256, SMEMSZ>>>(b1);
    gemm2_kernel<<<dim3(D_ / BN, T_ / BM, B_), 256, SMEMSZ>>>(x, b2, out);
}

// round 8
// speedup vs baseline: 1.4042x; 1.0378x over previous
#include <cuda_runtime.h>
#include <cuda_fp16.h>
#include <math.h>
#include <stdint.h>

#define B_ 32
#define T_ 1024
#define D_ 512
#define H_ 2048
#define E_ 8

#define BM 128
#define BN 128
#define BK 64                    // halves per k-tile (4 x k16 mma steps), 128B rows
#define STAGES 3

#define A_BYTES (BM * 128)                    // 16384
#define B_BYTES (BN * 128)                    // 16384
#define STAGE_BYTES (A_BYTES + B_BYTES)       // 32768
#define SMEMSZ (STAGES * STAGE_BYTES)         // 98304

#define NB_G1 (16 * 8 * 64)                   // 8192 gemm1 blocks
#define NB_G2 (4 * 8 * 32)                    // 1024 gemm2 blocks

// ---------------------------------------------------------------------------
// scratch (device globals — no allocation allowed)
// ---------------------------------------------------------------------------
__device__ int      g_eidx[B_][2];
__device__ float    g_prob[B_][2];
__device__ float    g_pool[B_][8][D_];
__device__ unsigned g_cnt[B_][8];                    // gemm1->gemm2 readiness
__device__ unsigned g_prep = 0;                      // pool-block completion counter
__device__ __half   g_xh[(size_t)B_ * T_ * D_];      // fp16 x
__device__ __half   g_w1t[(size_t)E_ * H_ * D_];     // w1^T [E][H][D] fp16
__device__ __half   g_w2t[(size_t)E_ * D_ * H_];     // w2^T [E][D][H] fp16
__device__ __half   g_h[(size_t)B_ * T_ * (2 * H_)]; // p*silu(x@w1+b1) fp16

// ---------------------------------------------------------------------------
// helpers
// ---------------------------------------------------------------------------
__device__ __forceinline__ uint32_t smem_u32(const void* p) {
    uint32_t a;
    asm("{ .reg .u64 t; cvta.to.shared.u64 t, %1; cvt.u32.u64 %0, t; }" : "=r"(a) : "l"(p));
    return a;
}
__device__ __forceinline__ void cp16(uint32_t dst, const void* src) {
    asm volatile("cp.async.cg.shared.global [%0], [%1], 16;" :: "r"(dst), "l"(src));
}
__device__ __forceinline__ void cp_commit() {
    asm volatile("cp.async.commit_group;" ::: "memory");
}
template <int N>
__device__ __forceinline__ void cp_wait() {
    asm volatile("cp.async.wait_group %0;" :: "n"(N) : "memory");
}
__device__ __forceinline__ void ldsm_x4(unsigned& r0, unsigned& r1, unsigned& r2,
                                        unsigned& r3, uint32_t addr) {
    asm volatile("ldmatrix.sync.aligned.m8n8.x4.shared.b16 {%0,%1,%2,%3}, [%4];"
        : "=r"(r0), "=r"(r1), "=r"(r2), "=r"(r3) : "r"(addr));
}
__device__ __forceinline__ void ldsm_x2(unsigned& r0, unsigned& r1, uint32_t addr) {
    asm volatile("ldmatrix.sync.aligned.m8n8.x2.shared.b16 {%0,%1}, [%2];"
        : "=r"(r0), "=r"(r1) : "r"(addr));
}
__device__ __forceinline__ void mma_f16(float* d, const unsigned* a, const unsigned* b) {
    asm volatile(
        "mma.sync.aligned.m16n8k16.row.col.f32.f16.f16.f32 "
        "{%0,%1,%2,%3}, {%4,%5,%6,%7}, {%8,%9}, {%0,%1,%2,%3};\n"
        : "+f"(d[0]), "+f"(d[1]), "+f"(d[2]), "+f"(d[3])
        : "r"(a[0]), "r"(a[1]), "r"(a[2]), "r"(a[3]), "r"(b[0]), "r"(b[1]));
}

// ---------------------------------------------------------------------------
// fused prep kernel: 4352 blocks x 512 threads
//   [0,256)      pool partials + fp16 x + g_cnt reset; last block computes gate
//   [256,2304)   w1 [E][D][H] -> w1t [E][H][D] fp16  (64x64 tiles)
//   [2304,4352)  w2 [E][H][D] -> w2t [E][D][H] fp16  (64x64 tiles)
// ---------------------------------------------------------------------------
__device__ __forceinline__ void transpose64(const float* __restrict__ S,
                                            __half* __restrict__ Dp,
                                            int R, int C, int r0, int c0,
                                            float (*tile)[65], int tid) {
    const int tx = tid & 63, ty = tid >> 6;     // ty 0..7
    #pragma unroll
    for (int i = 0; i < 8; i++) {
        const int row = ty + i * 8;
        tile[row][tx] = S[(size_t)(r0 + row) * C + c0 + tx];
    }
    __syncthreads();
    #pragma unroll
    for (int i = 0; i < 8; i++) {
        const int row = ty + i * 8;
        Dp[(size_t)(c0 + row) * R + r0 + tx] = __float2half_rn(tile[tx][row]);
    }
}

__global__ __launch_bounds__(512) void prep_kernel(const float* __restrict__ x,
                                                   const float* __restrict__ w1,
                                                   const float* __restrict__ w2,
                                                   const float* __restrict__ gw,
                                                   const float* __restrict__ gb,
                                                   float* __restrict__ out_logits) {
    __shared__ float tile[64][65];
    __shared__ float pooled[D_];
    __shared__ float logits[E_];
    __shared__ int   is_last;
    const int bid = blockIdx.x;
    const int tid = threadIdx.x;

    if (bid < 256) {
        // -------- pool + convert --------
        const int b = bid >> 3, ch = bid & 7;
        if (tid == 0) g_cnt[b][ch] = 0u;          // reset fusion counters for this run
        const int d = tid;
        const size_t base = ((size_t)b * T_ + (size_t)ch * 128) * D_ + d;
        float s = 0.f;
        for (int t = 0; t < 128; t++) {
            float v = x[base + (size_t)t * D_];
            s += v;
            g_xh[base + (size_t)t * D_] = __float2half_rn(v);
        }
        g_pool[b][ch][d] = s;
        __syncthreads();
        if (tid == 0) {
            __threadfence();
            is_last = (atomicAdd(&g_prep, 1u) == 255u) ? 1 : 0;
        }
        __syncthreads();
        if (is_last) {
            __threadfence();
            // -------- gate (512 threads) --------
            const int gb_ = tid;                  // reuse: one thread per d? need per-b
            (void)gb_;
            // loop over all 32 batches; 512 threads: b = tid>>4 handles... simpler:
            // do it with 16 threads per batch: b = tid >> 4, lane16 = tid & 15
            const int bb = tid >> 4, l16 = tid & 15;
            float lg[E_];
            if (bb < B_) {
                // pooled sum for this batch, strided across 16 lanes
                for (int e = 0; e < E_; e++) lg[e] = 0.f;
                for (int j = l16; j < D_; j += 16) {
                    float pv = 0.f;
                    #pragma unroll
                    for (int c = 0; c < 8; c++) pv += g_pool[bb][c][j];
                    pv *= (1.0f / (float)T_);
                    #pragma unroll
                    for (int e = 0; e < E_; e++) lg[e] += pv * gw[(size_t)j * E_ + e];
                }
                #pragma unroll
                for (int e = 0; e < E_; e++) {
                    #pragma unroll
                    for (int o = 8; o > 0; o >>= 1)
                        lg[e] += __shfl_xor_sync(0xffffffffu, lg[e], o);
                }
                if (l16 == 0) {
                    float lf[E_];
                    #pragma unroll
                    for (int e = 0; e < E_; e++) lf[e] = lg[e] + gb[e];
                    int i0 = 0; float l0 = lf[0];
                    #pragma unroll
                    for (int e = 1; e < E_; e++) if (lf[e] > l0) { l0 = lf[e]; i0 = e; }
                    int i1 = -1; float l1 = -1e30f;
                    #pragma unroll
                    for (int e = 0; e < E_; e++)
                        if (e != i0 && lf[e] > l1) { l1 = lf[e]; i1 = e; }
                    float e1 = expf(l1 - l0);
                    float inv = 1.0f / (1.0f + e1);
                    g_eidx[bb][0] = i0; g_eidx[bb][1] = i1;
                    g_prob[bb][0] = inv; g_prob[bb][1] = e1 * inv;
                    #pragma unroll
                    for (int e = 0; e < E_; e++) out_logits[bb * E_ + e] = lf[e];
                }
            }
            __syncthreads();
            if (tid == 0) g_prep = 0u;            // self-reset for graph replay
        }
        (void)pooled; (void)logits;
    } else if (bid < 256 + 2048) {
        // -------- w1 transpose: R=D, C=H --------
        const int idx = bid - 256;
        const int cx = idx & 31, cy = (idx >> 5) & 7, e = idx >> 8;
        transpose64(w1 + (size_t)e * D_ * H_, g_w1t + (size_t)e * H_ * D_,
                    D_, H_, cy * 64, cx * 64, tile, tid);
    } else {
        // -------- w2 transpose: R=H, C=D --------
        const int idx = bid - 2304;
        const int cx = idx & 7, cy = (idx >> 3) & 31, e = idx >> 8;
        transpose64(w2 + (size_t)e * H_ * D_, g_w2t + (size_t)e * D_ * H_,
                    H_, D_, cy * 64, cx * 64, tile, tid);
    }
}

// ---------------------------------------------------------------------------
// GEMM core: 256 threads, 8 warps 2(m)x4(n), warp tile 64x32, fp16 m16n8k16
// Tiles: 128 rows x 128B (64 halves), XOR-swizzled: chunk_phys = chunk ^ (row&7)
// ---------------------------------------------------------------------------

#define ISSUE_STAGE(slot, A_SRC, B_SRC) do {                                   \
    const uint32_t _as = sm_base + (slot) * STAGE_BYTES;                       \
    const uint32_t _bs = _as + A_BYTES;                                        \
    _Pragma("unroll")                                                          \
    for (int _i = 0; _i < 4; _i++) {                                           \
        const int _c = _i * 256 + tid;                                         \
        const int _r = _c >> 3, _lc = _c & 7;                                  \
        cp16(_as + _r * 128 + ((_lc ^ (_r & 7)) << 4), (A_SRC(_r, _lc)));      \
    }                                                                          \
    _Pragma("unroll")                                                          \
    for (int _i = 0; _i < 4; _i++) {                                           \
        const int _c = _i * 256 + tid;                                         \
        const int _r = _c >> 3, _lc = _c & 7;                                  \
        cp16(_bs + _r * 128 + ((_lc ^ (_r & 7)) << 4), (B_SRC(_r, _lc)));      \
    }                                                                          \
} while (0)

#define COMPUTE_STAGE(slot) do {                                               \
    const uint32_t _ab = sm_base + (slot) * STAGE_BYTES;                       \
    const uint32_t _bb = _ab + A_BYTES;                                        \
    _Pragma("unroll")                                                          \
    for (int ks = 0; ks < 4; ks++) {                                           \
        unsigned af[4][4], bf[4][2];                                           \
        _Pragma("unroll")                                                      \
        for (int mt = 0; mt < 4; mt++)                                         \
            ldsm_x4(af[mt][0], af[mt][1], af[mt][2], af[mt][3],                \
                    _ab + arow_off + mt * 2048 + (((2 * ks + ac) ^ sxor) << 4)); \
        _Pragma("unroll")                                                      \
        for (int nt = 0; nt < 4; nt++)                                         \
            ldsm_x2(bf[nt][0], bf[nt][1],                                      \
                    _bb + brow_off + nt * 1024 + (((2 * ks + bc) ^ sxor) << 4)); \
        _Pragma("unroll")                                                      \
        for (int mt = 0; mt < 4; mt++)                                         \
            _Pragma("unroll")                                                  \
            for (int nt = 0; nt < 4; nt++)                                     \
                mma_f16(acc[mt][nt], af[mt], bf[nt]);                          \
    }                                                                          \
} while (0)

#define GEMM_PIPELINE(NK, A_SRC, B_SRC) do {                                   \
    _Pragma("unroll")                                                          \
    for (int s = 0; s < STAGES - 1; s++) {                                     \
        const int kk = s;                                                      \
        ISSUE_STAGE(s, A_SRC, B_SRC);                                          \
        cp_commit();                                                           \
    }                                                                          \
    for (int kt = 0; kt < (NK); kt++) {                                        \
        cp_wait<STAGES - 2>();                                                 \
        __syncthreads();                                                       \
        const int pf = kt + STAGES - 1;                                        \
        if (pf < (NK)) {                                                       \
            const int kk = pf;                                                 \
            ISSUE_STAGE(pf % STAGES, A_SRC, B_SRC);                            \
        }                                                                      \
        cp_commit();                                                           \
        COMPUTE_STAGE(kt % STAGES);                                            \
    }                                                                          \
} while (0)

#define LANE_OFFS()                                                            \
    const int wm = (warp & 1) * 64;                                            \
    const int wn = (warp >> 1) * 32;                                           \
    const uint32_t arow_off = (uint32_t)(wm + (lane & 15)) * 128;              \
    const uint32_t ac = (uint32_t)(lane >> 4);                                 \
    const uint32_t brow_off = (uint32_t)(wn + (lane & 7)) * 128;               \
    const uint32_t bc = (uint32_t)((lane >> 3) & 1);                           \
    const uint32_t sxor = (uint32_t)(lane & 7);

// ---------------------------------------------------------------------------
// fused GEMM kernel: bids [0,8192) = gemm1, [8192,9216) = gemm2 (spins on g_cnt)
// ---------------------------------------------------------------------------
__global__ __launch_bounds__(256, 2) void gemm_fused(const float* __restrict__ b1,
                                                     const float* __restrict__ x,
                                                     const float* __restrict__ b2,
                                                     float* __restrict__ out) {
    extern __shared__ char smem[];
    const uint32_t sm_base = smem_u32(smem);
    const int bid = blockIdx.x;
    const int tid  = threadIdx.x;
    const int warp = tid >> 5, lane = tid & 31;
    LANE_OFFS();
    const int g = lane >> 2, t4 = lane & 3;

    float acc[4][4][4];
    #pragma unroll
    for (int i = 0; i < 4; i++)
        #pragma unroll
        for (int j = 0; j < 4; j++)
            #pragma unroll
            for (int r = 0; r < 4; r++) acc[i][j][r] = 0.f;

    if (bid < NB_G1) {
        // =============== GEMM1 ===============
        const int xt = bid & 15, yt = (bid >> 4) & 7, bz = bid >> 7;
        const int b = bz >> 1, slot = bz & 1;
        const int e = g_eidx[b][slot];
        const float p = g_prob[b][slot];
        const int m0 = yt * BM, n0 = xt * BN;

        const __half* Ag = g_xh  + ((size_t)b * T_ + m0) * D_;
        const __half* Bg = g_w1t + ((size_t)e * H_ + n0) * D_;

        #define A1(r, c) (Ag + (size_t)(r) * D_ + kk * BK + (c) * 8)
        #define B1(r, c) (Bg + (size_t)(r) * D_ + kk * BK + (c) * 8)
        GEMM_PIPELINE(D_ / BK, A1, B1);      // 8 k-tiles
        #undef A1
        #undef B1

        const float* brow = b1 + (size_t)e * H_ + n0;
        __half* Hb = g_h + ((size_t)b * T_ + m0) * (2 * H_) + (size_t)slot * H_ + n0;
        #pragma unroll
        for (int mt = 0; mt < 4; mt++) {
            #pragma unroll
            for (int nt = 0; nt < 4; nt++) {
                #pragma unroll
                for (int half = 0; half < 2; half++) {
                    const int row = wm + mt * 16 + g + half * 8;
                    const int col = wn + nt * 8 + t4 * 2;
                    float v0 = acc[mt][nt][half * 2 + 0] + brow[col];
                    float v1 = acc[mt][nt][half * 2 + 1] + brow[col + 1];
                    v0 = p * v0 * (1.0f / (1.0f + __expf(-v0)));
                    v1 = p * v1 * (1.0f / (1.0f + __expf(-v1)));
                    *(__half2*)&Hb[(size_t)row * (2 * H_) + col] =
                        __floats2half2_rn(v0, v1);
                }
            }
        }
        // release
        __syncthreads();
        if (tid == 0) {
            __threadfence();
            atomicAdd(&g_cnt[b][yt], 1u);
        }
    } else {
        // =============== GEMM2 ===============
        const int r2 = bid - NB_G1;
        const int xt = r2 & 3, yt = (r2 >> 2) & 7, b = r2 >> 5;
        const int m0 = yt * BM, n0 = xt * BN;

        // acquire: wait for the 32 gemm1 blocks covering (b, yt)
        if (tid == 0) {
            unsigned v;
            do {
                asm volatile("ld.global.acquire.gpu.u32 %0, [%1];"
                    : "=r"(v) : "l"(&g_cnt[b][yt]) : "memory");
                if (v < 32u) __nanosleep(128);
            } while (v < 32u);
        }
        __syncthreads();

        const int e0 = g_eidx[b][0], e1 = g_eidx[b][1];
        const float p0 = g_prob[b][0], p1 = g_prob[b][1];
        const __half* Ag  = g_h + ((size_t)b * T_ + m0) * (2 * H_);
        const __half* Bg0 = g_w2t + ((size_t)e0 * D_ + n0) * H_;
        const __half* Bg1 = g_w2t + ((size_t)e1 * D_ + n0) * H_;

        #define A2(r, c) (Ag + (size_t)(r) * (2 * H_) + kk * BK + (c) * 8)
        #define B2(r, c) ((kk < 32 ? Bg0 : Bg1) + (size_t)(r) * H_ + (kk & 31) * BK + (c) * 8)
        GEMM_PIPELINE((2 * H_) / BK, A2, B2);    // 64 k-tiles
        #undef A2
        #undef B2

        const float* b2r0 = b2 + (size_t)e0 * D_ + n0;
        const float* b2r1 = b2 + (size_t)e1 * D_ + n0;
        const float* xb = x   + ((size_t)b * T_ + m0) * D_ + n0;
        float*       ob = out + ((size_t)b * T_ + m0) * D_ + n0;
        #pragma unroll
        for (int mt = 0; mt < 4; mt++) {
            #pragma unroll
            for (int nt = 0; nt < 4; nt++) {
                #pragma unroll
                for (int half = 0; half < 2; half++) {
                    const int row = wm + mt * 16 + g + half * 8;
                    const int col = wn + nt * 8 + t4 * 2;
                    const float bias0 = p0 * b2r0[col]     + p1 * b2r1[col];
                    const float bias1 = p0 * b2r0[col + 1] + p1 * b2r1[col + 1];
                    const float2 xv = *(const float2*)&xb[(size_t)row * D_ + col];
                    float v0 = acc[mt][nt][half * 2 + 0] + bias0 + xv.x;
                    float v1 = acc[mt][nt][half * 2 + 1] + bias1 + xv.y;
                    *(float2*)&ob[(size_t)row * D_ + col] = make_float2(v0, v1);
                }
            }
        }
    }
}

// ---------------------------------------------------------------------------
extern "C" void kernel_launch(void* const* d_in, const int* in_sizes, int n_in,
                              void* d_out, int out_size) {
    const float* x  = (const float*)d_in[0];
    const float* gw = (const float*)d_in[1];
    const float* gb = (const float*)d_in[2];
    const float* w1 = (const float*)d_in[3];
    const float* b1 = (const float*)d_in[4];
    const float* w2 = (const float*)d_in[5];
    const float* b2 = (const float*)d_in[6];

    float* out = (float*)d_out;
    float* out_logits = out + (size_t)B_ * T_ * D_;

    cudaFuncSetAttribute(gemm_fused, cudaFuncAttributeMaxDynamicSharedMemorySize, SMEMSZ);

    prep_kernel<<<256 + 2048 + 2048, 512>>>(x, w1, w2, gw, gb, out_logits);
    gemm_fused<<<NB_G1 + NB_G2, 256, SMEMSZ>>>(b1, x, b2, out);
}